// round 7
// baseline (speedup 1.0000x reference)
#include <cuda_runtime.h>
#include <cuda_bf16.h>
#include <math.h>
#include <stdint.h>

#define NROWS 8192
#define FIN   128
#define FOUT  64
#define BI    64
#define BJ    128
#define TILES 64
#define L2E 1.4426950408889634f
#define PB  272                  // smem row pitch in bytes (136 bf16)

// attn smem map (bytes)
#define SM_P    0                // 2 bufs x (2 planes x 17408) = 69632
#define SM_WH   69632            // 3 bufs x 34816 = 104448
#define SM_W2R  174080           // 3 x 512
#define SM_LR   175616           // 256 floats
#define SM_TOTB 176640

typedef unsigned long long ull;

__device__ float g_Wh1[NROWS];
__device__ float g_Wh2[NROWS];
__device__ __nv_bfloat16 g_WhT_hi[FOUT * NROWS];
__device__ __nv_bfloat16 g_WhT_lo[FOUT * NROWS];

// ---- helpers ----------------------------------------------------------------
__device__ __forceinline__ uint32_t s2u(const void* p) {
    uint32_t a;
    asm("{.reg .u64 t; cvta.to.shared.u64 t,%1; cvt.u32.u64 %0,t;}" : "=r"(a) : "l"(p));
    return a;
}
__device__ __forceinline__ float ex2f(float x) {
    float y; asm("ex2.approx.ftz.f32 %0,%1;" : "=f"(y) : "f"(x)); return y;
}
__device__ __forceinline__ uint32_t bf2(float a, float b) {   // lo=a, hi=b
    uint32_t r; asm("cvt.rn.bf16x2.f32 %0,%2,%1;" : "=r"(r) : "f"(a), "f"(b)); return r;
}
__device__ __forceinline__ void cpasync16(uint32_t d, const void* s) {
    asm volatile("cp.async.cg.shared.global [%0],[%1],16;" :: "r"(d), "l"(s));
}
__device__ __forceinline__ void ldsm4(uint32_t* r, uint32_t a) {
    asm volatile("ldmatrix.sync.aligned.m8n8.x4.shared.b16 {%0,%1,%2,%3},[%4];"
                 : "=r"(r[0]), "=r"(r[1]), "=r"(r[2]), "=r"(r[3]) : "r"(a));
}
__device__ __forceinline__ void mmabf(float* d, const uint32_t* a, const uint32_t* b) {
    asm volatile("mma.sync.aligned.m16n8k16.row.col.f32.bf16.bf16.f32 "
                 "{%0,%1,%2,%3},{%4,%5,%6,%7},{%8,%9},{%0,%1,%2,%3};"
                 : "+f"(d[0]), "+f"(d[1]), "+f"(d[2]), "+f"(d[3])
                 : "r"(a[0]), "r"(a[1]), "r"(a[2]), "r"(a[3]), "r"(b[0]), "r"(b[1]));
}
__device__ __forceinline__ ull packf2(float a, float b) {
    ull r;
    asm("mov.b64 %0,{%1,%2};" : "=l"(r) : "r"(__float_as_uint(a)), "r"(__float_as_uint(b)));
    return r;
}
__device__ __forceinline__ void fmaf2(ull& acc, ull a, ull b) {
    asm("fma.rn.f32x2 %0,%1,%2,%0;" : "+l"(acc) : "l"(a), "l"(b));
}
__device__ __forceinline__ void unpackf2(ull v, float& lo, float& hi) {
    uint32_t l, h;
    asm("mov.b64 {%0,%1},%2;" : "=r"(l), "=r"(h) : "l"(v));
    lo = __uint_as_float(l); hi = __uint_as_float(h);
}

// phase-1: 16 cols of one row -> P hi/lo planes, accumulate lsum
__device__ __forceinline__ void phase1_store(char* ph, const int4* cur,
                                             const float4* w2, float wh1r,
                                             float& lsum) {
    const float NEGI = __int_as_float(0xff800000);
    uint32_t hi[8], lo[8];
#pragma unroll
    for (int k = 0; k < 4; k++) {
        int4 a4 = cur[k]; float4 wv = w2[k];
        float z, u, tt, p0, p1, p2, p3;
        z = wh1r + wv.x; u = z * L2E; tt = fmaxf(u, 0.2f * u);
        if (a4.x == 0) tt = NEGI; p0 = ex2f(tt);
        z = wh1r + wv.y; u = z * L2E; tt = fmaxf(u, 0.2f * u);
        if (a4.y == 0) tt = NEGI; p1 = ex2f(tt);
        z = wh1r + wv.z; u = z * L2E; tt = fmaxf(u, 0.2f * u);
        if (a4.z == 0) tt = NEGI; p2 = ex2f(tt);
        z = wh1r + wv.w; u = z * L2E; tt = fmaxf(u, 0.2f * u);
        if (a4.w == 0) tt = NEGI; p3 = ex2f(tt);
        lsum += (p0 + p1) + (p2 + p3);
        uint32_t h0 = bf2(p0, p1), h1 = bf2(p2, p3);
        float r0 = p0 - __uint_as_float(h0 << 16);
        float r1 = p1 - __uint_as_float(h0 & 0xffff0000u);
        float r2 = p2 - __uint_as_float(h1 << 16);
        float r3 = p3 - __uint_as_float(h1 & 0xffff0000u);
        hi[2 * k] = h0; hi[2 * k + 1] = h1;
        lo[2 * k] = bf2(r0, r1); lo[2 * k + 1] = bf2(r2, r3);
    }
    *(uint4*)ph = make_uint4(hi[0], hi[1], hi[2], hi[3]);
    *(uint4*)(ph + 16) = make_uint4(hi[4], hi[5], hi[6], hi[7]);
    *(uint4*)(ph + 17408) = make_uint4(lo[0], lo[1], lo[2], lo[3]);
    *(uint4*)(ph + 17408 + 16) = make_uint4(lo[4], lo[5], lo[6], lo[7]);
}

// ---------------------------------------------------------------------------
// Fused prep: Wh = x@W -> WhT hi/lo planes, Wh1, Wh2.
// ---------------------------------------------------------------------------
__global__ __launch_bounds__(256) void wh_fused(const float* __restrict__ x,
                                                const float* __restrict__ W,
                                                const float* __restrict__ a) {
    extern __shared__ float shm[];
    float* xs = shm;                  // 64 x 132
    float* Ws = shm + 8448;           // 128 x 64
    float* av = shm + 8448 + 8192;    // 128
    int tid = threadIdx.x;
    int row0 = blockIdx.x * 64;

    for (int u = tid; u < 2048; u += 256) {
        int rr = u >> 5, cc = u & 31;
        float4 v = ((const float4*)(x + (size_t)(row0 + rr) * FIN))[cc];
        *(float4*)(xs + rr * 132 + cc * 4) = v;
    }
    for (int u = tid; u < 2048; u += 256)
        ((float4*)Ws)[u] = ((const float4*)W)[u];
    if (tid < 128) av[tid] = a[tid];
    __syncthreads();

    int tr = tid >> 4, tc = tid & 15;
    ull acc[4][2] = {{0ull, 0ull}, {0ull, 0ull}, {0ull, 0ull}, {0ull, 0ull}};
    const ulonglong2* W2 = (const ulonglong2*)Ws;
#pragma unroll 4
    for (int k = 0; k < FIN; k++) {
        ulonglong2 wv = W2[k * 16 + tc];
#pragma unroll
        for (int i = 0; i < 4; i++) {
            float xv = xs[(tr * 4 + i) * 132 + k];
            ull xp = packf2(xv, xv);
            fmaf2(acc[i][0], xp, wv.x);
            fmaf2(acc[i][1], xp, wv.y);
        }
    }
    float o[4][4];
#pragma unroll
    for (int i = 0; i < 4; i++) {
        unpackf2(acc[i][0], o[i][0], o[i][1]);
        unpackf2(acc[i][1], o[i][2], o[i][3]);
    }
    __syncthreads();
    float* s2 = xs;                  // reuse: [64 f][pitch 65]
#pragma unroll
    for (int i = 0; i < 4; i++)
#pragma unroll
        for (int j = 0; j < 4; j++)
            s2[(tc * 4 + j) * 65 + tr * 4 + i] = o[i][j];
    __syncthreads();

    {
        int f = tid >> 2, seg = tid & 3;
        const float* src = s2 + f * 65 + seg * 16;
        uint32_t hi[8], lo[8];
#pragma unroll
        for (int j = 0; j < 8; j++) {
            float v0 = src[2 * j], v1 = src[2 * j + 1];
            uint32_t hh = bf2(v0, v1);
            float r0 = v0 - __uint_as_float(hh << 16);
            float r1 = v1 - __uint_as_float(hh & 0xffff0000u);
            hi[j] = hh; lo[j] = bf2(r0, r1);
        }
        size_t o0 = ((size_t)f * NROWS + row0 + seg * 16) * 2;
        *(uint4*)((char*)g_WhT_hi + o0) = make_uint4(hi[0], hi[1], hi[2], hi[3]);
        *(uint4*)((char*)g_WhT_hi + o0 + 16) = make_uint4(hi[4], hi[5], hi[6], hi[7]);
        *(uint4*)((char*)g_WhT_lo + o0) = make_uint4(lo[0], lo[1], lo[2], lo[3]);
        *(uint4*)((char*)g_WhT_lo + o0 + 16) = make_uint4(lo[4], lo[5], lo[6], lo[7]);
    }
    {
        int row = tid >> 2, sub = tid & 3;
        float s1 = 0.f, sB = 0.f;
#pragma unroll
        for (int k = 0; k < 16; k++) {
            int f = sub * 16 + k;
            float v = s2[f * 65 + row];
            s1 += v * av[f];
            sB += v * av[64 + f];
        }
        s1 += __shfl_xor_sync(0xffffffffu, s1, 1);
        s1 += __shfl_xor_sync(0xffffffffu, s1, 2);
        sB += __shfl_xor_sync(0xffffffffu, sB, 1);
        sB += __shfl_xor_sync(0xffffffffu, sB, 2);
        if (sub == 0) { g_Wh1[row0 + row] = s1; g_Wh2[row0 + row] = sB; }
    }
}

// ---------------------------------------------------------------------------
// attn: warp-specialized. Warps 0-7 producers (phase-1 + cp.async),
// warps 8-15 consumers (MMA, m32n32 tiles, 2-way K split).
// ---------------------------------------------------------------------------
__global__ __launch_bounds__(512, 1) void attn_kernel(const int* __restrict__ adj,
                                                      float* __restrict__ out) {
    extern __shared__ char smc[];
    uint32_t smb = s2u(smc);
    float* lred = (float*)(smc + SM_LR);

    int tid = threadIdx.x;
    int i0 = blockIdx.x * BI;
    int warp = tid >> 5, lane = tid & 31;
    bool is_prod = (warp < 8);

    // ---- producer state ----
    int r = tid >> 2, q = tid & 3;                    // valid for tid<256
    const int4* arow = (const int4*)adj + (size_t)(i0 + (r & 63)) * (NROWS / 4);
    float wh1r = is_prod ? g_Wh1[i0 + r] : 0.f;
    float lsum = 0.f;
    int4 cur[8];

    // cp.async geometry: 4 chunks/thread/plane (256 producers)
    uint32_t dsto[4], srco[4];
#pragma unroll
    for (int u = 0; u < 4; u++) {
        int idx = u * 256 + (tid & 255);
        int row = idx >> 4, ch = idx & 15;
        dsto[u] = (uint32_t)(row * PB + ch * 16);
        srco[u] = (uint32_t)((row * NROWS + ch * 8) * 2);
    }

    // ---- consumer state ----
    int cw = warp - 8;
    int mi = cw & 1, ni = (cw >> 1) & 1, kk = cw >> 2;
    uint32_t aoff = (uint32_t)((((lane & 7) + 8 * ((lane >> 3) & 1)) * PB) + (lane >> 4) * 16);
    uint32_t boff = (uint32_t)(((lane & 7) + 8 * (lane >> 4)) * PB + ((lane >> 3) & 1) * 16);
    uint32_t aBase = smb + SM_P + (uint32_t)(mi * 32) * PB + aoff;
    uint32_t bBase = smb + SM_WH + (uint32_t)(ni * 32) * PB + boff;
    float acc[2][4][4];
#pragma unroll
    for (int i = 0; i < 2; i++)
#pragma unroll
        for (int j = 0; j < 4; j++)
#pragma unroll
            for (int v = 0; v < 4; v++) acc[i][j][v] = 0.f;

    // ---- prologue (producers) ----
    if (is_prod) {
        const char* ph = (const char*)g_WhT_hi;
        const char* pl = (const char*)g_WhT_lo;
#pragma unroll
        for (int b = 0; b < 2; b++) {
            uint32_t d0 = smb + SM_WH + b * 34816;
#pragma unroll
            for (int u = 0; u < 4; u++) cpasync16(d0 + dsto[u], ph + srco[u] + b * 256);
#pragma unroll
            for (int u = 0; u < 4; u++) cpasync16(d0 + 17408 + dsto[u], pl + srco[u] + b * 256);
            if (tid < 32)
                cpasync16(smb + SM_W2R + b * 512 + tid * 16, (const char*)g_Wh2 + b * 512 + tid * 16);
            asm volatile("cp.async.commit_group;" ::: "memory");
        }
        // phase-1 tile 0 (w2, adj direct from gmem)
        int4 a0[8];
#pragma unroll
        for (int k = 0; k < 8; k++) a0[k] = arow[q * 8 + k];
        float4 w2a[8];
#pragma unroll
        for (int k = 0; k < 8; k++) w2a[k] = ((const float4*)g_Wh2)[q * 8 + k];
        char* pdst = smc + SM_P + r * PB + q * 64;
        phase1_store(pdst, a0, w2a, wh1r, lsum);
        phase1_store(pdst + 32, a0 + 4, w2a + 4, wh1r, lsum);
        // prefetch adj(1)
#pragma unroll
        for (int k = 0; k < 8; k++) cur[k] = arow[32 + q * 8 + k];
        asm volatile("cp.async.wait_group 1;" ::: "memory");
    }
    __syncthreads();

    // ---- main loop ----
    for (int t = 0; t < TILES; ++t) {
        if (is_prod) {
            // cp.async for (t+2)
            if (t < 62) {
                int jq = t + 2;
                uint32_t d0 = smb + SM_WH + (uint32_t)(jq % 3) * 34816;
                const char* ph = (const char*)g_WhT_hi;
                const char* pl = (const char*)g_WhT_lo;
                uint32_t j2 = (uint32_t)jq * 256;
#pragma unroll
                for (int u = 0; u < 4; u++) cpasync16(d0 + dsto[u], ph + srco[u] + j2);
#pragma unroll
                for (int u = 0; u < 4; u++) cpasync16(d0 + 17408 + dsto[u], pl + srco[u] + j2);
                if (tid < 32)
                    cpasync16(smb + SM_W2R + (uint32_t)(jq % 3) * 512 + tid * 16,
                              (const char*)g_Wh2 + jq * 512 + tid * 16);
                asm volatile("cp.async.commit_group;" ::: "memory");
                asm volatile("cp.async.wait_group 1;" ::: "memory");
            } else {
                asm volatile("cp.async.wait_group 0;" ::: "memory");
            }
            // phase-1(t+1)
            if (t < 63) {
                int4 nxt[8];
                if (t < 62) {
                    int jq = t + 2;
#pragma unroll
                    for (int k = 0; k < 8; k++) nxt[k] = arow[jq * 32 + q * 8 + k];
                }
                const float4* w2p = (const float4*)(smc + SM_W2R + ((t + 1) % 3) * 512) + q * 8;
                char* pdst = smc + SM_P + ((t + 1) & 1) * 34816 + r * PB + q * 64;
                float4 w2a[8];
#pragma unroll
                for (int k = 0; k < 8; k++) w2a[k] = w2p[k];
                phase1_store(pdst, cur, w2a, wh1r, lsum);
                phase1_store(pdst + 32, cur + 4, w2a + 4, wh1r, lsum);
                if (t < 62) {
#pragma unroll
                    for (int k = 0; k < 8; k++) cur[k] = nxt[k];
                }
            }
        } else {
            // ---- consumer: MMA(t) ----
            uint32_t aB = aBase + (uint32_t)(t & 1) * 34816, aL = aB + 17408;
            uint32_t wB = bBase + (uint32_t)(t % 3) * 34816, wL = wB + 17408;
#pragma unroll
            for (int j = 0; j < 4; j++) {
                uint32_t ko = (uint32_t)(kk * 4 + j) * 32;
                uint32_t ah0[4], ah1[4], al0[4], al1[4];
                uint32_t bh0[4], bh1[4], bl0[4], bl1[4];
                ldsm4(ah0, aB + ko); ldsm4(ah1, aB + 16 * PB + ko);
                ldsm4(bh0, wB + ko); ldsm4(bh1, wB + 16 * PB + ko);
                ldsm4(al0, aL + ko); ldsm4(al1, aL + 16 * PB + ko);
                ldsm4(bl0, wL + ko); ldsm4(bl1, wL + 16 * PB + ko);
                mmabf(acc[0][0], ah0, bh0 + 0); mmabf(acc[0][1], ah0, bh0 + 2);
                mmabf(acc[0][2], ah0, bh1 + 0); mmabf(acc[0][3], ah0, bh1 + 2);
                mmabf(acc[1][0], ah1, bh0 + 0); mmabf(acc[1][1], ah1, bh0 + 2);
                mmabf(acc[1][2], ah1, bh1 + 0); mmabf(acc[1][3], ah1, bh1 + 2);
                mmabf(acc[0][0], ah0, bl0 + 0); mmabf(acc[0][1], ah0, bl0 + 2);
                mmabf(acc[0][2], ah0, bl1 + 0); mmabf(acc[0][3], ah0, bl1 + 2);
                mmabf(acc[1][0], ah1, bl0 + 0); mmabf(acc[1][1], ah1, bl0 + 2);
                mmabf(acc[1][2], ah1, bl1 + 0); mmabf(acc[1][3], ah1, bl1 + 2);
                mmabf(acc[0][0], al0, bh0 + 0); mmabf(acc[0][1], al0, bh0 + 2);
                mmabf(acc[0][2], al0, bh1 + 0); mmabf(acc[0][3], al0, bh1 + 2);
                mmabf(acc[1][0], al1, bh0 + 0); mmabf(acc[1][1], al1, bh0 + 2);
                mmabf(acc[1][2], al1, bh1 + 0); mmabf(acc[1][3], al1, bh1 + 2);
            }
        }
        __syncthreads();
    }

    // ---- epilogue ----
    if (is_prod) lred[tid] = lsum;
    __syncthreads();

    float* Outq = (float*)(smc + SM_P) + (mi * 2 + ni) * 1088;   // 32x34 floats
    if (!is_prod && kk == 1) {
#pragma unroll
        for (int m2 = 0; m2 < 2; m2++)
#pragma unroll
            for (int nb = 0; nb < 4; nb++) {
                int rl = m2 * 16 + (lane >> 2);
                int cl = nb * 8 + (lane & 3) * 2;
                *(float2*)(Outq + rl * 34 + cl) = make_float2(acc[m2][nb][0], acc[m2][nb][1]);
                *(float2*)(Outq + (rl + 8) * 34 + cl) = make_float2(acc[m2][nb][2], acc[m2][nb][3]);
            }
    }
    __syncthreads();
    if (!is_prod && kk == 0) {
#pragma unroll
        for (int m2 = 0; m2 < 2; m2++) {
            int rl = mi * 32 + m2 * 16 + (lane >> 2);
            float la = (lred[rl * 4 + 0] + lred[rl * 4 + 1]) +
                       (lred[rl * 4 + 2] + lred[rl * 4 + 3]);
            float lb = (lred[(rl + 8) * 4 + 0] + lred[(rl + 8) * 4 + 1]) +
                       (lred[(rl + 8) * 4 + 2] + lred[(rl + 8) * 4 + 3]);
            float inv0 = 1.0f / la, inv1 = 1.0f / lb;
            int rq = m2 * 16 + (lane >> 2);
#pragma unroll
            for (int nb = 0; nb < 4; nb++) {
                int cl = nb * 8 + (lane & 3) * 2;
                float2 o0 = *(float2*)(Outq + rq * 34 + cl);
                float2 o1 = *(float2*)(Outq + (rq + 8) * 34 + cl);
                float v0 = (acc[m2][nb][0] + o0.x) * inv0;
                float v1 = (acc[m2][nb][1] + o0.y) * inv0;
                float v2 = (acc[m2][nb][2] + o1.x) * inv1;
                float v3 = (acc[m2][nb][3] + o1.y) * inv1;
                v0 = v0 > 0.f ? v0 : (__expf(v0) - 1.f);
                v1 = v1 > 0.f ? v1 : (__expf(v1) - 1.f);
                v2 = v2 > 0.f ? v2 : (__expf(v2) - 1.f);
                v3 = v3 > 0.f ? v3 : (__expf(v3) - 1.f);
                int col = ni * 32 + cl;
                *(float2*)(out + (size_t)(i0 + rl) * FOUT + col) = make_float2(v0, v1);
                *(float2*)(out + (size_t)(i0 + rl + 8) * FOUT + col) = make_float2(v2, v3);
            }
        }
    }
}

// ---------------------------------------------------------------------------
extern "C" void kernel_launch(void* const* d_in, const int* in_sizes, int n_in,
                              void* d_out, int out_size) {
    const float* x   = (const float*)d_in[0];
    const int*   adj = (const int*)d_in[1];
    const float* W   = (const float*)d_in[2];
    const float* a   = (const float*)d_in[3];
    float* out = (float*)d_out;

    size_t smem_wh = (size_t)(8448 + 8192 + 128) * sizeof(float);
    static int attr_set = 0;
    if (!attr_set) {
        cudaFuncSetAttribute(wh_fused, cudaFuncAttributeMaxDynamicSharedMemorySize,
                             (int)smem_wh);
        cudaFuncSetAttribute(attn_kernel, cudaFuncAttributeMaxDynamicSharedMemorySize,
                             SM_TOTB);
        attr_set = 1;
    }

    wh_fused<<<NROWS / 64, 256, smem_wh>>>(x, W, a);
    attn_kernel<<<NROWS / BI, 512, SM_TOTB>>>(adj, out);
}

// round 8
// speedup vs baseline: 1.2969x; 1.2969x over previous
#include <cuda_runtime.h>
#include <cuda_bf16.h>
#include <math.h>
#include <stdint.h>

#define NROWS 8192
#define FIN   128
#define FOUT  64
#define BI    32
#define BJ    128
#define TILES 64
#define L2E 1.4426950408889634f
#define PB   272                 // smem row pitch in bytes (136 bf16)
#define PLO  8704                // P lo-plane offset (32 rows * 272)

// attn smem map (bytes)
#define SM_P    0                // 2 bufs x (2 planes x 8704) = 34816
#define SM_WH   34816            // 2 bufs x 34816 = 69632
#define SM_LR   104448           // 256 floats
#define SM_TOTB 105472

typedef unsigned long long ull;

__device__ float g_Wh1[NROWS];
__device__ float g_Wh2[NROWS];
__device__ __nv_bfloat16 g_WhT_hi[FOUT * NROWS];
__device__ __nv_bfloat16 g_WhT_lo[FOUT * NROWS];

// ---- helpers ----------------------------------------------------------------
__device__ __forceinline__ uint32_t s2u(const void* p) {
    uint32_t a;
    asm("{.reg .u64 t; cvta.to.shared.u64 t,%1; cvt.u32.u64 %0,t;}" : "=r"(a) : "l"(p));
    return a;
}
__device__ __forceinline__ float ex2f(float x) {
    float y; asm("ex2.approx.ftz.f32 %0,%1;" : "=f"(y) : "f"(x)); return y;
}
__device__ __forceinline__ uint32_t bf2(float a, float b) {   // lo=a, hi=b
    uint32_t r; asm("cvt.rn.bf16x2.f32 %0,%2,%1;" : "=r"(r) : "f"(a), "f"(b)); return r;
}
__device__ __forceinline__ void cpasync16(uint32_t d, const void* s) {
    asm volatile("cp.async.cg.shared.global [%0],[%1],16;" :: "r"(d), "l"(s));
}
__device__ __forceinline__ void ldsm4(uint32_t* r, uint32_t a) {
    asm volatile("ldmatrix.sync.aligned.m8n8.x4.shared.b16 {%0,%1,%2,%3},[%4];"
                 : "=r"(r[0]), "=r"(r[1]), "=r"(r[2]), "=r"(r[3]) : "r"(a));
}
__device__ __forceinline__ void mmabf(float* d, const uint32_t* a, const uint32_t* b) {
    asm volatile("mma.sync.aligned.m16n8k16.row.col.f32.bf16.bf16.f32 "
                 "{%0,%1,%2,%3},{%4,%5,%6,%7},{%8,%9},{%0,%1,%2,%3};"
                 : "+f"(d[0]), "+f"(d[1]), "+f"(d[2]), "+f"(d[3])
                 : "r"(a[0]), "r"(a[1]), "r"(a[2]), "r"(a[3]), "r"(b[0]), "r"(b[1]));
}
__device__ __forceinline__ ull packf2(float a, float b) {
    ull r;
    asm("mov.b64 %0,{%1,%2};" : "=l"(r) : "r"(__float_as_uint(a)), "r"(__float_as_uint(b)));
    return r;
}
__device__ __forceinline__ void fmaf2(ull& acc, ull a, ull b) {
    asm("fma.rn.f32x2 %0,%1,%2,%0;" : "+l"(acc) : "l"(a), "l"(b));
}
__device__ __forceinline__ void unpackf2(ull v, float& lo, float& hi) {
    uint32_t l, h;
    asm("mov.b64 {%0,%1},%2;" : "=r"(l), "=r"(h) : "l"(v));
    lo = __uint_as_float(l); hi = __uint_as_float(h);
}

// phase-1: 16 cols of one row -> P hi/lo planes (lo at +PLO), accumulate lsum
__device__ __forceinline__ void phase1_store(char* ph, const int4* cur,
                                             const float4* w2, float wh1r,
                                             float& lsum) {
    const float NEGI = __int_as_float(0xff800000);
    uint32_t hi[8], lo[8];
#pragma unroll
    for (int k = 0; k < 4; k++) {
        int4 a4 = cur[k]; float4 wv = w2[k];
        float z, u, tt, p0, p1, p2, p3;
        z = wh1r + wv.x; u = z * L2E; tt = fmaxf(u, 0.2f * u);
        if (a4.x == 0) tt = NEGI; p0 = ex2f(tt);
        z = wh1r + wv.y; u = z * L2E; tt = fmaxf(u, 0.2f * u);
        if (a4.y == 0) tt = NEGI; p1 = ex2f(tt);
        z = wh1r + wv.z; u = z * L2E; tt = fmaxf(u, 0.2f * u);
        if (a4.z == 0) tt = NEGI; p2 = ex2f(tt);
        z = wh1r + wv.w; u = z * L2E; tt = fmaxf(u, 0.2f * u);
        if (a4.w == 0) tt = NEGI; p3 = ex2f(tt);
        lsum += (p0 + p1) + (p2 + p3);
        uint32_t h0 = bf2(p0, p1), h1 = bf2(p2, p3);
        float r0 = p0 - __uint_as_float(h0 << 16);
        float r1 = p1 - __uint_as_float(h0 & 0xffff0000u);
        float r2 = p2 - __uint_as_float(h1 << 16);
        float r3 = p3 - __uint_as_float(h1 & 0xffff0000u);
        hi[2 * k] = h0; hi[2 * k + 1] = h1;
        lo[2 * k] = bf2(r0, r1); lo[2 * k + 1] = bf2(r2, r3);
    }
    *(uint4*)ph = make_uint4(hi[0], hi[1], hi[2], hi[3]);
    *(uint4*)(ph + 16) = make_uint4(hi[4], hi[5], hi[6], hi[7]);
    *(uint4*)(ph + PLO) = make_uint4(lo[0], lo[1], lo[2], lo[3]);
    *(uint4*)(ph + PLO + 16) = make_uint4(lo[4], lo[5], lo[6], lo[7]);
}

// ---------------------------------------------------------------------------
// Fused prep: Wh = x@W -> WhT hi/lo planes, Wh1, Wh2.  (unchanged, ~14us)
// ---------------------------------------------------------------------------
__global__ __launch_bounds__(256) void wh_fused(const float* __restrict__ x,
                                                const float* __restrict__ W,
                                                const float* __restrict__ a) {
    extern __shared__ float shm[];
    float* xs = shm;                  // 64 x 132
    float* Ws = shm + 8448;           // 128 x 64
    float* av = shm + 8448 + 8192;    // 128
    int tid = threadIdx.x;
    int row0 = blockIdx.x * 64;

    for (int u = tid; u < 2048; u += 256) {
        int rr = u >> 5, cc = u & 31;
        float4 v = ((const float4*)(x + (size_t)(row0 + rr) * FIN))[cc];
        *(float4*)(xs + rr * 132 + cc * 4) = v;
    }
    for (int u = tid; u < 2048; u += 256)
        ((float4*)Ws)[u] = ((const float4*)W)[u];
    if (tid < 128) av[tid] = a[tid];
    __syncthreads();

    int tr = tid >> 4, tc = tid & 15;
    ull acc[4][2] = {{0ull, 0ull}, {0ull, 0ull}, {0ull, 0ull}, {0ull, 0ull}};
    const ulonglong2* W2 = (const ulonglong2*)Ws;
#pragma unroll 4
    for (int k = 0; k < FIN; k++) {
        ulonglong2 wv = W2[k * 16 + tc];
#pragma unroll
        for (int i = 0; i < 4; i++) {
            float xv = xs[(tr * 4 + i) * 132 + k];
            ull xp = packf2(xv, xv);
            fmaf2(acc[i][0], xp, wv.x);
            fmaf2(acc[i][1], xp, wv.y);
        }
    }
    float o[4][4];
#pragma unroll
    for (int i = 0; i < 4; i++) {
        unpackf2(acc[i][0], o[i][0], o[i][1]);
        unpackf2(acc[i][1], o[i][2], o[i][3]);
    }
    __syncthreads();
    float* s2 = xs;                  // reuse: [64 f][pitch 65]
#pragma unroll
    for (int i = 0; i < 4; i++)
#pragma unroll
        for (int j = 0; j < 4; j++)
            s2[(tc * 4 + j) * 65 + tr * 4 + i] = o[i][j];
    __syncthreads();

    {
        int f = tid >> 2, seg = tid & 3;
        const float* src = s2 + f * 65 + seg * 16;
        uint32_t hi[8], lo[8];
#pragma unroll
        for (int j = 0; j < 8; j++) {
            float v0 = src[2 * j], v1 = src[2 * j + 1];
            uint32_t hh = bf2(v0, v1);
            float r0 = v0 - __uint_as_float(hh << 16);
            float r1 = v1 - __uint_as_float(hh & 0xffff0000u);
            hi[j] = hh; lo[j] = bf2(r0, r1);
        }
        size_t o0 = ((size_t)f * NROWS + row0 + seg * 16) * 2;
        *(uint4*)((char*)g_WhT_hi + o0) = make_uint4(hi[0], hi[1], hi[2], hi[3]);
        *(uint4*)((char*)g_WhT_hi + o0 + 16) = make_uint4(hi[4], hi[5], hi[6], hi[7]);
        *(uint4*)((char*)g_WhT_lo + o0) = make_uint4(lo[0], lo[1], lo[2], lo[3]);
        *(uint4*)((char*)g_WhT_lo + o0 + 16) = make_uint4(lo[4], lo[5], lo[6], lo[7]);
    }
    {
        int row = tid >> 2, sub = tid & 3;
        float s1 = 0.f, sB = 0.f;
#pragma unroll
        for (int k = 0; k < 16; k++) {
            int f = sub * 16 + k;
            float v = s2[f * 65 + row];
            s1 += v * av[f];
            sB += v * av[64 + f];
        }
        s1 += __shfl_xor_sync(0xffffffffu, s1, 1);
        s1 += __shfl_xor_sync(0xffffffffu, s1, 2);
        sB += __shfl_xor_sync(0xffffffffu, sB, 1);
        sB += __shfl_xor_sync(0xffffffffu, sB, 2);
        if (sub == 0) { g_Wh1[row0 + row] = s1; g_Wh2[row0 + row] = sB; }
    }
}

// ---------------------------------------------------------------------------
// attn: BI=32, grid 256, 2 blocks/SM (cross-block pipe overlap).
// 8 warps = 2 m16-strips x 2 n32-halves x 2-way K-split.
// ---------------------------------------------------------------------------
__global__ __launch_bounds__(256, 2) void attn_kernel(const int* __restrict__ adj,
                                                      float* __restrict__ out) {
    extern __shared__ char smc[];
    uint32_t smb = s2u(smc);
    float* lred = (float*)(smc + SM_LR);

    int tid = threadIdx.x;
    int i0 = blockIdx.x * BI;
    int warp = tid >> 5, lane = tid & 31;

    // phase-1 mapping: 8 threads/row, 16 cols each
    int r = tid >> 3, q = tid & 7;
    const int4* arow = (const int4*)adj + (size_t)(i0 + r) * (NROWS / 4);
    float wh1r = g_Wh1[i0 + r];
    float lsum = 0.f;

    // mma mapping
    int mi = warp & 1, ni = (warp >> 1) & 1, kk = warp >> 2;
    uint32_t aoff = (uint32_t)((((lane & 7) + 8 * ((lane >> 3) & 1)) * PB) + (lane >> 4) * 16);
    uint32_t boff = (uint32_t)(((lane & 7) + 8 * (lane >> 4)) * PB + ((lane >> 3) & 1) * 16);
    uint32_t aBase = smb + SM_P + (uint32_t)(mi * 16) * PB + aoff;
    uint32_t bBase = smb + SM_WH + (uint32_t)(ni * 32) * PB + boff;
    float acc[4][4];
#pragma unroll
    for (int i = 0; i < 4; i++)
#pragma unroll
        for (int j = 0; j < 4; j++) acc[i][j] = 0.f;

    // cp.async geometry: 4 chunks/thread/plane
    uint32_t dsto[4], srco[4];
#pragma unroll
    for (int u = 0; u < 4; u++) {
        int idx = u * 256 + tid;
        int row = idx >> 4, ch = idx & 15;
        dsto[u] = (uint32_t)(row * PB + ch * 16);
        srco[u] = (uint32_t)((row * NROWS + ch * 8) * 2);
    }

    // ---- prologue: Wh(0) -> buf0 (group 0); adj(0) regs ----
    {
        const char* ph = (const char*)g_WhT_hi;
        const char* pl = (const char*)g_WhT_lo;
        uint32_t d0 = smb + SM_WH;
#pragma unroll
        for (int u = 0; u < 4; u++) cpasync16(d0 + dsto[u], ph + srco[u]);
#pragma unroll
        for (int u = 0; u < 4; u++) cpasync16(d0 + 17408 + dsto[u], pl + srco[u]);
        asm volatile("cp.async.commit_group;" ::: "memory");
    }
    int4 cur[4], nxt[4];
#pragma unroll
    for (int k = 0; k < 4; k++) cur[k] = arow[q * 4 + k];

    for (int t = 0; t < TILES; ++t) {
        // prefetch adj(t+1)
        if (t < 63) {
#pragma unroll
            for (int k = 0; k < 4; k++) nxt[k] = arow[((t + 1) << 5) + q * 4 + k];
        }
        // ---- phase 1(t) -> P[t&1]; w2 straight from gmem (L1/L2-hot) ----
        {
            float4 w2a[4];
#pragma unroll
            for (int k = 0; k < 4; k++) w2a[k] = ((const float4*)g_Wh2)[(t << 5) + q * 4 + k];
            char* pdst = smc + SM_P + (t & 1) * 17408 + r * PB + q * 32;
            phase1_store(pdst, cur, w2a, wh1r, lsum);
        }
        __syncthreads();   // A: P[t&1] written; all warps past MMA(t-1)

        // ---- cp.async Wh(t+1) -> buf (t+1)&1 ----
        if (t < 63) {
            uint32_t d0 = smb + SM_WH + (uint32_t)((t + 1) & 1) * 34816;
            const char* ph = (const char*)g_WhT_hi;
            const char* pl = (const char*)g_WhT_lo;
            uint32_t j2 = (uint32_t)(t + 1) * 256;
#pragma unroll
            for (int u = 0; u < 4; u++) cpasync16(d0 + dsto[u], ph + srco[u] + j2);
#pragma unroll
            for (int u = 0; u < 4; u++) cpasync16(d0 + 17408 + dsto[u], pl + srco[u] + j2);
            asm volatile("cp.async.commit_group;" ::: "memory");
            asm volatile("cp.async.wait_group 1;" ::: "memory");   // Wh(t) landed
        } else {
            asm volatile("cp.async.wait_group 0;" ::: "memory");
        }
        __syncthreads();   // B: P + Wh(t) visible to all

        // ---- MMA(t): P[t&1] x Wh[t&1], k-chunks [kk*4, kk*4+4) ----
        {
            uint32_t aB = aBase + (uint32_t)(t & 1) * 17408, aL = aB + PLO;
            uint32_t wB = bBase + (uint32_t)(t & 1) * 34816, wL = wB + 17408;
#pragma unroll
            for (int j = 0; j < 4; j++) {
                uint32_t ko = (uint32_t)(kk * 4 + j) * 32;
                uint32_t ah[4], al[4], bh0[4], bh1[4], bl0[4], bl1[4];
                ldsm4(ah, aB + ko); ldsm4(al, aL + ko);
                ldsm4(bh0, wB + ko); ldsm4(bh1, wB + 16 * PB + ko);
                ldsm4(bl0, wL + ko); ldsm4(bl1, wL + 16 * PB + ko);
                mmabf(acc[0], ah, bh0 + 0); mmabf(acc[1], ah, bh0 + 2);
                mmabf(acc[2], ah, bh1 + 0); mmabf(acc[3], ah, bh1 + 2);
                mmabf(acc[0], ah, bl0 + 0); mmabf(acc[1], ah, bl0 + 2);
                mmabf(acc[2], ah, bl1 + 0); mmabf(acc[3], ah, bl1 + 2);
                mmabf(acc[0], al, bh0 + 0); mmabf(acc[1], al, bh0 + 2);
                mmabf(acc[2], al, bh1 + 0); mmabf(acc[3], al, bh1 + 2);
            }
        }
#pragma unroll
        for (int k = 0; k < 4; k++) cur[k] = nxt[k];
    }

    // ---- epilogue: k-split reduce + normalize + ELU ----
    lred[tid] = lsum;
    __syncthreads();

    float* Red = (float*)(smc + SM_P);   // 32 x 66 floats (8448 B)
    if (kk == 1) {
#pragma unroll
        for (int nb = 0; nb < 4; nb++) {
            int rl = mi * 16 + (lane >> 2);
            int cl = ni * 32 + nb * 8 + (lane & 3) * 2;
            *(float2*)(Red + rl * 66 + cl) = make_float2(acc[nb][0], acc[nb][1]);
            *(float2*)(Red + (rl + 8) * 66 + cl) = make_float2(acc[nb][2], acc[nb][3]);
        }
    }
    __syncthreads();
    if (kk == 0) {
        int rl = mi * 16 + (lane >> 2);
        float4 A = *(float4*)&lred[rl * 8];
        float4 B = *(float4*)&lred[rl * 8 + 4];
        float la = ((A.x + A.y) + (A.z + A.w)) + ((B.x + B.y) + (B.z + B.w));
        float4 C = *(float4*)&lred[(rl + 8) * 8];
        float4 D = *(float4*)&lred[(rl + 8) * 8 + 4];
        float lb = ((C.x + C.y) + (C.z + C.w)) + ((D.x + D.y) + (D.z + D.w));
        float inv0 = 1.0f / la, inv1 = 1.0f / lb;
#pragma unroll
        for (int nb = 0; nb < 4; nb++) {
            int cl = ni * 32 + nb * 8 + (lane & 3) * 2;
            float2 o0 = *(float2*)(Red + rl * 66 + cl);
            float2 o1 = *(float2*)(Red + (rl + 8) * 66 + cl);
            float v0 = (acc[nb][0] + o0.x) * inv0;
            float v1 = (acc[nb][1] + o0.y) * inv0;
            float v2 = (acc[nb][2] + o1.x) * inv1;
            float v3 = (acc[nb][3] + o1.y) * inv1;
            v0 = v0 > 0.f ? v0 : (__expf(v0) - 1.f);
            v1 = v1 > 0.f ? v1 : (__expf(v1) - 1.f);
            v2 = v2 > 0.f ? v2 : (__expf(v2) - 1.f);
            v3 = v3 > 0.f ? v3 : (__expf(v3) - 1.f);
            *(float2*)(out + (size_t)(i0 + rl) * FOUT + cl) = make_float2(v0, v1);
            *(float2*)(out + (size_t)(i0 + rl + 8) * FOUT + cl) = make_float2(v2, v3);
        }
    }
}

// ---------------------------------------------------------------------------
extern "C" void kernel_launch(void* const* d_in, const int* in_sizes, int n_in,
                              void* d_out, int out_size) {
    const float* x   = (const float*)d_in[0];
    const int*   adj = (const int*)d_in[1];
    const float* W   = (const float*)d_in[2];
    const float* a   = (const float*)d_in[3];
    float* out = (float*)d_out;

    size_t smem_wh = (size_t)(8448 + 8192 + 128) * sizeof(float);
    static int attr_set = 0;
    if (!attr_set) {
        cudaFuncSetAttribute(wh_fused, cudaFuncAttributeMaxDynamicSharedMemorySize,
                             (int)smem_wh);
        cudaFuncSetAttribute(attn_kernel, cudaFuncAttributeMaxDynamicSharedMemorySize,
                             SM_TOTB);
        attr_set = 1;
    }

    wh_fused<<<NROWS / 64, 256, smem_wh>>>(x, W, a);
    attn_kernel<<<NROWS / BI, 256, SM_TOTB>>>(adj, out);
}

// round 9
// speedup vs baseline: 1.8505x; 1.4269x over previous
#include <cuda_runtime.h>
#include <cuda_bf16.h>
#include <math.h>
#include <stdint.h>

#define NROWS 8192
#define FIN   128
#define FOUT  64
#define BI    32
#define TILES 64
#define L2E 1.4426950408889634f
#define PB   272                 // WhT smem row pitch in bytes (136 bf16)

// attn smem map (bytes): Wh 2 bufs x (2 planes x 17408) = 69632, lred 512
#define SM_WH   0
#define SM_LR   69632
#define SM_TOTB 70144

typedef unsigned long long ull;

__device__ float g_Wh1[NROWS];
__device__ float g_Wh2[NROWS];
__device__ __nv_bfloat16 g_WhT_hi[FOUT * NROWS];
__device__ __nv_bfloat16 g_WhT_lo[FOUT * NROWS];

// ---- helpers ----------------------------------------------------------------
__device__ __forceinline__ uint32_t s2u(const void* p) {
    uint32_t a;
    asm("{.reg .u64 t; cvta.to.shared.u64 t,%1; cvt.u32.u64 %0,t;}" : "=r"(a) : "l"(p));
    return a;
}
__device__ __forceinline__ float ex2f(float x) {
    float y; asm("ex2.approx.ftz.f32 %0,%1;" : "=f"(y) : "f"(x)); return y;
}
__device__ __forceinline__ uint32_t bf2(float a, float b) {   // lo=a, hi=b
    uint32_t r; asm("cvt.rn.bf16x2.f32 %0,%2,%1;" : "=r"(r) : "f"(a), "f"(b)); return r;
}
__device__ __forceinline__ void cpasync16(uint32_t d, const void* s) {
    asm volatile("cp.async.cg.shared.global [%0],[%1],16;" :: "r"(d), "l"(s));
}
__device__ __forceinline__ void ldsm4(uint32_t* r, uint32_t a) {
    asm volatile("ldmatrix.sync.aligned.m8n8.x4.shared.b16 {%0,%1,%2,%3},[%4];"
                 : "=r"(r[0]), "=r"(r[1]), "=r"(r[2]), "=r"(r[3]) : "r"(a));
}
__device__ __forceinline__ void mmabf(float* d, const uint32_t* a, const uint32_t* b) {
    asm volatile("mma.sync.aligned.m16n8k16.row.col.f32.bf16.bf16.f32 "
                 "{%0,%1,%2,%3},{%4,%5,%6,%7},{%8,%9},{%0,%1,%2,%3};"
                 : "+f"(d[0]), "+f"(d[1]), "+f"(d[2]), "+f"(d[3])
                 : "r"(a[0]), "r"(a[1]), "r"(a[2]), "r"(a[3]), "r"(b[0]), "r"(b[1]));
}
__device__ __forceinline__ ull packf2(float a, float b) {
    ull r;
    asm("mov.b64 %0,{%1,%2};" : "=l"(r) : "r"(__float_as_uint(a)), "r"(__float_as_uint(b)));
    return r;
}
__device__ __forceinline__ void fmaf2(ull& acc, ull a, ull b) {
    asm("fma.rn.f32x2 %0,%1,%2,%0;" : "+l"(acc) : "l"(a), "l"(b));
}
__device__ __forceinline__ void unpackf2(ull v, float& lo, float& hi) {
    uint32_t l, h;
    asm("mov.b64 {%0,%1},%2;" : "=r"(l), "=r"(h) : "l"(v));
    lo = __uint_as_float(l); hi = __uint_as_float(h);
}

// masked exp: p = adj ? 2^(max(zL2, 0.2*zL2)) : 0
__device__ __forceinline__ float mexp(float wh1, float wh2, int a) {
    float z = (wh1 + wh2) * L2E;
    float t = fmaxf(z, 0.2f * z);
    if (a == 0) t = __int_as_float(0xff800000);
    return ex2f(t);
}

// ---------------------------------------------------------------------------
// Fused prep: Wh = x@W -> WhT hi/lo planes, Wh1, Wh2.
// ---------------------------------------------------------------------------
__global__ __launch_bounds__(256) void wh_fused(const float* __restrict__ x,
                                                const float* __restrict__ W,
                                                const float* __restrict__ a) {
    extern __shared__ float shm[];
    float* xs = shm;                  // 64 x 132
    float* Ws = shm + 8448;           // 128 x 64
    float* av = shm + 8448 + 8192;    // 128
    int tid = threadIdx.x;
    int row0 = blockIdx.x * 64;

    for (int u = tid; u < 2048; u += 256) {
        int rr = u >> 5, cc = u & 31;
        float4 v = ((const float4*)(x + (size_t)(row0 + rr) * FIN))[cc];
        *(float4*)(xs + rr * 132 + cc * 4) = v;
    }
    for (int u = tid; u < 2048; u += 256)
        ((float4*)Ws)[u] = ((const float4*)W)[u];
    if (tid < 128) av[tid] = a[tid];
    __syncthreads();

    int tr = tid >> 4, tc = tid & 15;
    ull acc[4][2] = {{0ull, 0ull}, {0ull, 0ull}, {0ull, 0ull}, {0ull, 0ull}};
    const ulonglong2* W2 = (const ulonglong2*)Ws;
#pragma unroll 4
    for (int k = 0; k < FIN; k++) {
        ulonglong2 wv = W2[k * 16 + tc];
#pragma unroll
        for (int i = 0; i < 4; i++) {
            float xv = xs[(tr * 4 + i) * 132 + k];
            ull xp = packf2(xv, xv);
            fmaf2(acc[i][0], xp, wv.x);
            fmaf2(acc[i][1], xp, wv.y);
        }
    }
    float o[4][4];
#pragma unroll
    for (int i = 0; i < 4; i++) {
        unpackf2(acc[i][0], o[i][0], o[i][1]);
        unpackf2(acc[i][1], o[i][2], o[i][3]);
    }
    __syncthreads();
    float* s2 = xs;                  // reuse: [64 f][pitch 65]
#pragma unroll
    for (int i = 0; i < 4; i++)
#pragma unroll
        for (int j = 0; j < 4; j++)
            s2[(tc * 4 + j) * 65 + tr * 4 + i] = o[i][j];
    __syncthreads();

    {
        int f = tid >> 2, seg = tid & 3;
        const float* src = s2 + f * 65 + seg * 16;
        uint32_t hi[8], lo[8];
#pragma unroll
        for (int j = 0; j < 8; j++) {
            float v0 = src[2 * j], v1 = src[2 * j + 1];
            uint32_t hh = bf2(v0, v1);
            float r0 = v0 - __uint_as_float(hh << 16);
            float r1 = v1 - __uint_as_float(hh & 0xffff0000u);
            hi[j] = hh; lo[j] = bf2(r0, r1);
        }
        size_t o0 = ((size_t)f * NROWS + row0 + seg * 16) * 2;
        *(uint4*)((char*)g_WhT_hi + o0) = make_uint4(hi[0], hi[1], hi[2], hi[3]);
        *(uint4*)((char*)g_WhT_hi + o0 + 16) = make_uint4(hi[4], hi[5], hi[6], hi[7]);
        *(uint4*)((char*)g_WhT_lo + o0) = make_uint4(lo[0], lo[1], lo[2], lo[3]);
        *(uint4*)((char*)g_WhT_lo + o0 + 16) = make_uint4(lo[4], lo[5], lo[6], lo[7]);
    }
    {
        int row = tid >> 2, sub = tid & 3;
        float s1 = 0.f, sB = 0.f;
#pragma unroll
        for (int k = 0; k < 16; k++) {
            int f = sub * 16 + k;
            float v = s2[f * 65 + row];
            s1 += v * av[f];
            sB += v * av[64 + f];
        }
        s1 += __shfl_xor_sync(0xffffffffu, s1, 1);
        s1 += __shfl_xor_sync(0xffffffffu, s1, 2);
        sB += __shfl_xor_sync(0xffffffffu, sB, 1);
        sB += __shfl_xor_sync(0xffffffffu, sB, 2);
        if (sub == 0) { g_Wh1[row0 + row] = s1; g_Wh2[row0 + row] = sB; }
    }
}

// ---------------------------------------------------------------------------
// attn: BI=32, grid 256, 2 blocks/SM. 8 warps = 2m x 4k; n=64 unsplit.
// Phase-1 computes P directly in A-fragment registers (no P smem, no A ldsm).
// ---------------------------------------------------------------------------
__global__ __launch_bounds__(256, 2) void attn_kernel(const int* __restrict__ adj,
                                                      float* __restrict__ out) {
    extern __shared__ char smc[];
    uint32_t smb = s2u(smc);
    float* lred = (float*)(smc + SM_LR);      // [4 kk][32 rows]

    int tid = threadIdx.x;
    int warp = tid >> 5, lane = tid & 31;
    int g = lane >> 2, tg = lane & 3;
    int mi = warp & 1, kk = warp >> 1;        // 2 m-strips x 4 k-chunks
    int i0 = blockIdx.x * BI;
    int row0 = i0 + mi * 16 + g;              // thread's two rows: row0, row0+8

    const int* ar0 = adj + (size_t)row0 * NROWS;
    const int* ar1 = ar0 + (size_t)8 * NROWS;
    float wh1a = g_Wh1[row0];
    float wh1b = g_Wh1[row0 + 8];

    // B ldsm addressing (proven layout)
    uint32_t boff = (uint32_t)(((lane & 7) + 8 * (lane >> 4)) * PB + ((lane >> 3) & 1) * 16);
    uint32_t bBase = smb + SM_WH + boff + (uint32_t)kk * 64;   // + buf*34816 + ng*16*PB + plane*17408 + step*32

    float acc[8][4];
#pragma unroll
    for (int i = 0; i < 8; i++)
#pragma unroll
        for (int j = 0; j < 4; j++) acc[i][j] = 0.f;

    // cp.async geometry: 4 chunks/thread/plane
    uint32_t dsto[4], srco[4];
#pragma unroll
    for (int u = 0; u < 4; u++) {
        int idx = u * 256 + tid;
        int row = idx >> 4, ch = idx & 15;
        dsto[u] = (uint32_t)(row * PB + ch * 16);
        srco[u] = (uint32_t)((row * NROWS + ch * 8) * 2);
    }

    // prologue: cp.async Wh(0) -> buf0
    {
        const char* ph = (const char*)g_WhT_hi;
        const char* pl = (const char*)g_WhT_lo;
        uint32_t d0 = smb + SM_WH;
#pragma unroll
        for (int u = 0; u < 4; u++) cpasync16(d0 + dsto[u], ph + srco[u]);
#pragma unroll
        for (int u = 0; u < 4; u++) cpasync16(d0 + 17408 + dsto[u], pl + srco[u]);
        asm volatile("cp.async.commit_group;" ::: "memory");
    }

    float lsum0 = 0.f, lsum1 = 0.f;

    for (int t = 0; t < TILES; ++t) {
        // ---- phase 1: A fragments in registers ----
        uint32_t ah[2][4], al[2][4];
        int jb = (t << 7) + kk * 32;
#pragma unroll
        for (int s = 0; s < 4; s++) {          // s = step*2 + half
            int cj = jb + s * 8 + tg * 2;
            int2 A0 = *(const int2*)(ar0 + cj);
            int2 A1 = *(const int2*)(ar1 + cj);
            float2 w2 = *(const float2*)(g_Wh2 + cj);
            float p00 = mexp(wh1a, w2.x, A0.x);
            float p01 = mexp(wh1a, w2.y, A0.y);
            float p10 = mexp(wh1b, w2.x, A1.x);
            float p11 = mexp(wh1b, w2.y, A1.y);
            lsum0 += p00 + p01;
            lsum1 += p10 + p11;
            uint32_t h0 = bf2(p00, p01);
            uint32_t h1 = bf2(p10, p11);
            float r00 = p00 - __uint_as_float(h0 << 16);
            float r01 = p01 - __uint_as_float(h0 & 0xffff0000u);
            float r10 = p10 - __uint_as_float(h1 << 16);
            float r11 = p11 - __uint_as_float(h1 & 0xffff0000u);
            int st = s >> 1, hf = s & 1;
            ah[st][hf * 2 + 0] = h0;
            ah[st][hf * 2 + 1] = h1;
            al[st][hf * 2 + 0] = bf2(r00, r01);
            al[st][hf * 2 + 1] = bf2(r10, r11);
        }

        // ---- Wh(t) ready; release buffers ----
        asm volatile("cp.async.wait_group 0;" ::: "memory");
        __syncthreads();
        if (t < 63) {
            uint32_t d0 = smb + SM_WH + (uint32_t)((t + 1) & 1) * 34816;
            const char* ph = (const char*)g_WhT_hi;
            const char* pl = (const char*)g_WhT_lo;
            uint32_t j2 = (uint32_t)(t + 1) * 256;
#pragma unroll
            for (int u = 0; u < 4; u++) cpasync16(d0 + dsto[u], ph + srco[u] + j2);
#pragma unroll
            for (int u = 0; u < 4; u++) cpasync16(d0 + 17408 + dsto[u], pl + srco[u] + j2);
            asm volatile("cp.async.commit_group;" ::: "memory");
        }

        // ---- MMA(t): A regs x Wh[t&1] ----
        uint32_t wB = bBase + (uint32_t)(t & 1) * 34816;
#pragma unroll
        for (int st = 0; st < 2; st++) {
            uint32_t ko = (uint32_t)st * 32;
#pragma unroll
            for (int ng = 0; ng < 4; ng++) {
                uint32_t bh[4], bl[4];
                uint32_t ba = wB + (uint32_t)ng * (16 * PB) + ko;
                ldsm4(bh, ba);
                ldsm4(bl, ba + 17408);
                mmabf(acc[2 * ng + 0], ah[st], bh + 0);
                mmabf(acc[2 * ng + 1], ah[st], bh + 2);
                mmabf(acc[2 * ng + 0], ah[st], bl + 0);
                mmabf(acc[2 * ng + 1], ah[st], bl + 2);
                mmabf(acc[2 * ng + 0], al[st], bh + 0);
                mmabf(acc[2 * ng + 1], al[st], bh + 2);
            }
        }
    }

    // ---- epilogue ----
    lsum0 += __shfl_xor_sync(0xffffffffu, lsum0, 1);
    lsum0 += __shfl_xor_sync(0xffffffffu, lsum0, 2);
    lsum1 += __shfl_xor_sync(0xffffffffu, lsum1, 1);
    lsum1 += __shfl_xor_sync(0xffffffffu, lsum1, 2);
    if (tg == 0) {
        lred[kk * 32 + mi * 16 + g] = lsum0;
        lred[kk * 32 + mi * 16 + 8 + g] = lsum1;
    }
    __syncthreads();

    float* Red = (float*)(smc + SM_WH);   // reuse buf0: 2 arrays of 32x66 floats
    int rl = mi * 16 + g;
    if (kk == 1 || kk == 3) {
        float* R = Red + (kk >> 1) * 2112;
#pragma unroll
        for (int nb = 0; nb < 8; nb++) {
            int cl = nb * 8 + tg * 2;
            *(float2*)(R + rl * 66 + cl) = make_float2(acc[nb][0], acc[nb][1]);
            *(float2*)(R + (rl + 8) * 66 + cl) = make_float2(acc[nb][2], acc[nb][3]);
        }
    }
    __syncthreads();
    if (kk == 0 || kk == 2) {
        float* R = Red + (kk >> 1) * 2112;
#pragma unroll
        for (int nb = 0; nb < 8; nb++) {
            int cl = nb * 8 + tg * 2;
            float2 o0 = *(float2*)(R + rl * 66 + cl);
            float2 o1 = *(float2*)(R + (rl + 8) * 66 + cl);
            acc[nb][0] += o0.x; acc[nb][1] += o0.y;
            acc[nb][2] += o1.x; acc[nb][3] += o1.y;
        }
    }
    __syncthreads();
    if (kk == 2) {
        float* R = Red + 2112;
#pragma unroll
        for (int nb = 0; nb < 8; nb++) {
            int cl = nb * 8 + tg * 2;
            *(float2*)(R + rl * 66 + cl) = make_float2(acc[nb][0], acc[nb][1]);
            *(float2*)(R + (rl + 8) * 66 + cl) = make_float2(acc[nb][2], acc[nb][3]);
        }
    }
    __syncthreads();
    if (kk == 0) {
        float la = lred[rl] + lred[32 + rl] + lred[64 + rl] + lred[96 + rl];
        float lb = lred[rl + 8] + lred[32 + rl + 8] + lred[64 + rl + 8] + lred[96 + rl + 8];
        float inv0 = 1.0f / la, inv1 = 1.0f / lb;
        float* R = Red + 2112;
#pragma unroll
        for (int nb = 0; nb < 8; nb++) {
            int cl = nb * 8 + tg * 2;
            float2 o0 = *(float2*)(R + rl * 66 + cl);
            float2 o1 = *(float2*)(R + (rl + 8) * 66 + cl);
            float v0 = (acc[nb][0] + o0.x) * inv0;
            float v1 = (acc[nb][1] + o0.y) * inv0;
            float v2 = (acc[nb][2] + o1.x) * inv1;
            float v3 = (acc[nb][3] + o1.y) * inv1;
            v0 = v0 > 0.f ? v0 : (__expf(v0) - 1.f);
            v1 = v1 > 0.f ? v1 : (__expf(v1) - 1.f);
            v2 = v2 > 0.f ? v2 : (__expf(v2) - 1.f);
            v3 = v3 > 0.f ? v3 : (__expf(v3) - 1.f);
            *(float2*)(out + (size_t)(i0 + rl) * FOUT + cl) = make_float2(v0, v1);
            *(float2*)(out + (size_t)(i0 + rl + 8) * FOUT + cl) = make_float2(v2, v3);
        }
    }
}

// ---------------------------------------------------------------------------
extern "C" void kernel_launch(void* const* d_in, const int* in_sizes, int n_in,
                              void* d_out, int out_size) {
    const float* x   = (const float*)d_in[0];
    const int*   adj = (const int*)d_in[1];
    const float* W   = (const float*)d_in[2];
    const float* a   = (const float*)d_in[3];
    float* out = (float*)d_out;

    size_t smem_wh = (size_t)(8448 + 8192 + 128) * sizeof(float);
    static int attr_set = 0;
    if (!attr_set) {
        cudaFuncSetAttribute(wh_fused, cudaFuncAttributeMaxDynamicSharedMemorySize,
                             (int)smem_wh);
        cudaFuncSetAttribute(attn_kernel, cudaFuncAttributeMaxDynamicSharedMemorySize,
                             SM_TOTB);
        attr_set = 1;
    }

    wh_fused<<<NROWS / 64, 256, smem_wh>>>(x, W, a);
    attn_kernel<<<NROWS / BI, 256, SM_TOTB>>>(adj, out);
}